// round 2
// baseline (speedup 1.0000x reference)
#include <cuda_runtime.h>
#include <cstdint>

// Problem constants (match reference)
#define N_NODES 4096
#define N_EDGES 131072
#define N_BITS  (N_NODES * N_NODES)           // 16,777,216 bits
#define N_WORDS (N_BITS / 32)                 // 524,288 uint32 words (2 MiB)

// Device-global scratch (no allocations allowed in kernel_launch)
__device__ uint32_t           g_bits[N_WORDS];
__device__ unsigned long long g_nnz;
__device__ unsigned int       g_trace;

// --- Kernel 1: clear bitmask + counters -------------------------------------
__global__ void k_clear(void) {
    int idx = blockIdx.x * blockDim.x + threadIdx.x;
    uint4* p = reinterpret_cast<uint4*>(g_bits);
    if (idx < N_WORDS / 4) {
        p[idx] = make_uint4(0u, 0u, 0u, 0u);
    }
    if (idx == 0) {
        g_nnz = 0ull;
        g_trace = 0u;
    }
}

// --- Kernel 2: scatter edges into bitmask (symmetric) -----------------------
// edge_index is int32, shape [2, N_EDGES] row-major.
__global__ void k_scatter(const int* __restrict__ ei) {
    int e = blockIdx.x * blockDim.x + threadIdx.x;
    if (e >= N_EDGES) return;
    unsigned i = (unsigned)ei[e];
    unsigned j = (unsigned)ei[e + N_EDGES];
    // Defensive bounds check: if the dtype model is wrong, finish with a
    // wrong answer (rel_err diagnoses it) instead of an illegal access.
    if (i >= (unsigned)N_NODES || j >= (unsigned)N_NODES) return;
    unsigned b0 = i * (unsigned)N_NODES + j;
    unsigned b1 = j * (unsigned)N_NODES + i;
    atomicOr(&g_bits[b0 >> 5], 1u << (b0 & 31u));
    if (b1 != b0)
        atomicOr(&g_bits[b1 >> 5], 1u << (b1 & 31u));
}

// --- Kernel 3: popcount reduce -> g_nnz -------------------------------------
__global__ void k_reduce_nnz(void) {
    __shared__ unsigned int ssum[8];  // one per warp (256 threads)
    unsigned int acc = 0;
    const uint4* p = reinterpret_cast<const uint4*>(g_bits);
    const int nvec = N_WORDS / 4;
    for (int idx = blockIdx.x * blockDim.x + threadIdx.x; idx < nvec;
         idx += gridDim.x * blockDim.x) {
        uint4 v = p[idx];
        acc += __popc(v.x) + __popc(v.y) + __popc(v.z) + __popc(v.w);
    }
    for (int off = 16; off > 0; off >>= 1)
        acc += __shfl_down_sync(0xFFFFFFFFu, acc, off);
    int lane = threadIdx.x & 31;
    int wid  = threadIdx.x >> 5;
    if (lane == 0) ssum[wid] = acc;
    __syncthreads();
    if (wid == 0) {
        unsigned int a = (lane < (blockDim.x >> 5)) ? ssum[lane] : 0u;
        for (int off = 16; off > 0; off >>= 1)
            a += __shfl_down_sync(0xFFFFFFFFu, a, off);
        if (lane == 0) atomicAdd(&g_nnz, (unsigned long long)a);
    }
}

// --- Kernel 4: diagonal (trace) ---------------------------------------------
__global__ void k_reduce_trace(void) {
    int i = blockIdx.x * blockDim.x + threadIdx.x;
    unsigned int bit = 0;
    if (i < N_NODES) {
        unsigned b = (unsigned)i * (unsigned)(N_NODES + 1);  // i*4096 + i
        bit = (g_bits[b >> 5] >> (b & 31u)) & 1u;
    }
    unsigned int mask = __ballot_sync(0xFFFFFFFFu, bit != 0);
    if ((threadIdx.x & 31) == 0 && mask)
        atomicAdd(&g_trace, (unsigned int)__popc(mask));
}

// --- Kernel 5: final loss ----------------------------------------------------
__global__ void k_final(float* __restrict__ out) {
    // var(lambda, ddof=1) = (sum(lambda^2) - (sum lambda)^2 / n) / (n - 1)
    // sum(lambda)   = trace(A)   = g_trace
    // sum(lambda^2) = trace(A^2) = nnz(A)  (0/1 symmetric matrix)
    double nnz = (double)g_nnz;
    double t   = (double)g_trace;
    double n   = (double)N_NODES;
    double var = (nnz - (t * t) / n) / (n - 1.0);
    out[0] = (float)(1.0 * var);  // WEIGHT = 1.0
}

extern "C" void kernel_launch(void* const* d_in, const int* in_sizes, int n_in,
                              void* d_out, int out_size) {
    (void)in_sizes; (void)n_in; (void)out_size;
    const int* edge_index = (const int*)d_in[1];
    float* out = (float*)d_out;

    k_clear<<<(N_WORDS / 4 + 255) / 256, 256>>>();
    k_scatter<<<(N_EDGES + 255) / 256, 256>>>(edge_index);
    k_reduce_nnz<<<296, 256>>>();
    k_reduce_trace<<<(N_NODES + 255) / 256, 256>>>();
    k_final<<<1, 1>>>(out);
}

// round 3
// speedup vs baseline: 1.0417x; 1.0417x over previous
#include <cuda_runtime.h>
#include <cstdint>

// Problem constants (match reference)
#define N_NODES 4096
#define N_EDGES 131072
#define N_BITS  (N_NODES * N_NODES)           // 16,777,216 bits
#define N_WORDS (N_BITS / 32)                 // 524,288 uint32 words (2 MiB)

// Device-global scratch. Zero-initialized at module load; Kernel B restores
// the all-zero invariant after every replay, so Kernel A can assume it.
__device__ uint32_t           g_bits[N_WORDS];
__device__ unsigned long long g_nnz;
__device__ unsigned int       g_trace;

// --- Kernel A: scatter edges + count newly-set bits --------------------------
// edge_index is int32, shape [2, N_EDGES] row-major.
__global__ void k_scatter_count(const int* __restrict__ ei) {
    int e = blockIdx.x * blockDim.x + threadIdx.x;
    unsigned new0 = 0, new1 = 0;
    if (e < N_EDGES) {
        unsigned i = (unsigned)ei[e];
        unsigned j = (unsigned)ei[e + N_EDGES];
        if (i < (unsigned)N_NODES && j < (unsigned)N_NODES) {
            unsigned b0 = i * (unsigned)N_NODES + j;
            unsigned m0 = 1u << (b0 & 31u);
            unsigned old0 = atomicOr(&g_bits[b0 >> 5], m0);
            new0 = (old0 & m0) ? 0u : 1u;
            if (i != j) {
                unsigned b1 = j * (unsigned)N_NODES + i;
                unsigned m1 = 1u << (b1 & 31u);
                unsigned old1 = atomicOr(&g_bits[b1 >> 5], m1);
                new1 = (old1 & m1) ? 0u : 1u;
            } else if (new0) {
                // newly-discovered self-loop -> contributes 1 to trace
                atomicAdd(&g_trace, 1u);
            }
        }
    }
    // Warp-aggregate the new-bit count -> one atomic per warp
    unsigned cnt = new0 + new1;
    for (int off = 16; off > 0; off >>= 1)
        cnt += __shfl_down_sync(0xFFFFFFFFu, cnt, off);
    if ((threadIdx.x & 31) == 0 && cnt)
        atomicAdd(&g_nnz, (unsigned long long)cnt);
}

// --- Kernel B: compute final loss, then clear touched words ------------------
__global__ void k_final_clear(const int* __restrict__ ei,
                              float* __restrict__ out) {
    int e = blockIdx.x * blockDim.x + threadIdx.x;

    if (e == 0) {
        // var(lambda, ddof=1) = (tr(A^2) - tr(A)^2 / n) / (n - 1)
        // tr(A)   = g_trace (distinct self-loop nodes)
        // tr(A^2) = nnz(A)  (0/1 symmetric matrix)
        double nnz = (double)g_nnz;
        double t   = (double)g_trace;
        double n   = (double)N_NODES;
        out[0] = (float)((nnz - (t * t) / n) / (n - 1.0));  // WEIGHT = 1.0
        // reset counters for next replay
        g_nnz = 0ull;
        g_trace = 0u;
    }

    if (e < N_EDGES) {
        unsigned i = (unsigned)ei[e];
        unsigned j = (unsigned)ei[e + N_EDGES];
        if (i < (unsigned)N_NODES && j < (unsigned)N_NODES) {
            unsigned b0 = i * (unsigned)N_NODES + j;
            unsigned b1 = j * (unsigned)N_NODES + i;
            // Plain full-word stores: idempotent, clears every touched word.
            g_bits[b0 >> 5] = 0u;
            g_bits[b1 >> 5] = 0u;
        }
    }
}

extern "C" void kernel_launch(void* const* d_in, const int* in_sizes, int n_in,
                              void* d_out, int out_size) {
    (void)in_sizes; (void)n_in; (void)out_size;
    const int* edge_index = (const int*)d_in[1];
    float* out = (float*)d_out;

    k_scatter_count<<<(N_EDGES + 255) / 256, 256>>>(edge_index);
    k_final_clear<<<(N_EDGES + 255) / 256, 256>>>(edge_index, out);
}

// round 4
// speedup vs baseline: 1.2461x; 1.1963x over previous
#include <cuda_runtime.h>
#include <cstdint>

// Problem constants (match reference)
#define N_NODES 4096
#define N_EDGES 131072
#define GRID    512
#define BLOCK   256
// GRID*BLOCK == N_EDGES exactly

// 64 MiB epoch-stamp array: cell (i,j) holds the epoch of the last replay
// that set it. "Set" test = atomicMax(cell, cur_epoch) < cur_epoch.
// Zero-initialized at module load; never cleared (epochs only grow).
__device__ uint32_t           g_cell[N_NODES * N_NODES];
__device__ uint32_t           g_epoch;   // completed-replay count
__device__ unsigned long long g_nnz;
__device__ unsigned int       g_trace;
__device__ unsigned int       g_done;    // monotone block-completion ticket

__global__ void __launch_bounds__(BLOCK)
k_graph_loss(const int* __restrict__ ei, float* __restrict__ out) {
    const int e = blockIdx.x * BLOCK + threadIdx.x;   // exact cover of edges

    // Epoch for THIS replay. Only updated by the last block of the previous
    // replay, strictly after all of that replay's blocks finished -> every
    // thread here reads the same value.
    const uint32_t cur = g_epoch + 1u;

    unsigned i = (unsigned)ei[e];
    unsigned j = (unsigned)ei[e + N_EDGES];

    unsigned cnt = 0;
    if (i < (unsigned)N_NODES && j < (unsigned)N_NODES) {
        unsigned c0   = i * (unsigned)N_NODES + j;
        unsigned old0 = atomicMax(&g_cell[c0], cur);
        unsigned new0 = (old0 < cur) ? 1u : 0u;
        cnt = new0;
        if (i != j) {
            unsigned c1 = j * (unsigned)N_NODES + i;
            cnt += (atomicMax(&g_cell[c1], cur) < cur) ? 1u : 0u;
        } else if (new0) {
            // newly-discovered self-loop this replay -> +1 to trace
            atomicAdd(&g_trace, 1u);
        }
    }

    // Warp reduce, then block reduce -> one atomicAdd per block
    #pragma unroll
    for (int off = 16; off > 0; off >>= 1)
        cnt += __shfl_down_sync(0xFFFFFFFFu, cnt, off);

    __shared__ unsigned s_warp[BLOCK / 32];
    const int lane = threadIdx.x & 31;
    const int wid  = threadIdx.x >> 5;
    if (lane == 0) s_warp[wid] = cnt;
    __syncthreads();

    if (threadIdx.x == 0) {
        unsigned bsum = 0;
        #pragma unroll
        for (int w = 0; w < BLOCK / 32; w++) bsum += s_warp[w];
        atomicAdd(&g_nnz, (unsigned long long)bsum);

        // Last-block-done pattern: fence my contributions, take a ticket.
        __threadfence();
        unsigned ticket = atomicAdd(&g_done, 1u);
        if ((ticket + 1u) % (unsigned)GRID == 0u) {
            // I am the last block of this replay: all blocks' nnz/trace
            // atomics are fence-ordered before their ticket increments.
            double nnz = (double)atomicAdd(&g_nnz, 0ull);
            double t   = (double)atomicAdd(&g_trace, 0u);
            double n   = (double)N_NODES;
            // var(eigvalsh(A), ddof=1) = (tr(A^2) - tr(A)^2/n) / (n-1)
            // tr(A) = #self-loop nodes; tr(A^2) = nnz (0/1 symmetric A)
            out[0] = (float)((nnz - (t * t) / n) / (n - 1.0));  // WEIGHT=1
            // Reset accumulators and advance the epoch for the next replay.
            g_nnz   = 0ull;
            g_trace = 0u;
            g_epoch = cur;
            __threadfence();
        }
    }
}

extern "C" void kernel_launch(void* const* d_in, const int* in_sizes, int n_in,
                              void* d_out, int out_size) {
    (void)in_sizes; (void)n_in; (void)out_size;
    const int* edge_index = (const int*)d_in[1];
    float* out = (float*)d_out;
    k_graph_loss<<<GRID, BLOCK>>>(edge_index, out);
}